// round 6
// baseline (speedup 1.0000x reference)
#include <cuda_runtime.h>
#include <math.h>

// ---- problem constants ----
#define NPK   10
#define LLEN  14
#define EMB   128
#define HH    160
#define WW    160
#define NBC   32
#define NGRID 36
#define NPOS  (NGRID*NGRID)
#define NUNIT (NPOS*NBC)    // 41472
#define NROW  (NUNIT*NPK)   // 414720
#define SEV   0x07070707

// ---- static scratch ----
__device__ float g_patches[(size_t)NROW * 49];
__device__ float g_den[(size_t)NROW * 49];
__device__ int4  g_cp[NUNIT * 2];   // [2u]=x-bytes(10+2 pad 0xC8), [2u+1]=y-bytes
__device__ float g_Wc[49 * 52];
__device__ float g_bias[NPK * 49];

#define PACK2(d, lo, hi) asm("mov.b64 %0, {%1, %2};" : "=l"(d) : "f"(lo), "f"(hi))
#define UNPK2(lo, hi, s) asm("mov.b64 {%0, %1}, %2;" : "=f"(lo), "=f"(hi) : "l"(s))
#define FMA2(d, a, b, c) asm("fma.rn.f32x2 %0, %1, %2, %3;" : "=l"(d) : "l"(a), "l"(b), "l"(c))

// ============================================================
// K0: fold projections
// ============================================================
__global__ void prep_kernel(const float* __restrict__ Wp, const float* __restrict__ bp,
                            const float* __restrict__ pe, const float* __restrict__ Wb,
                            const float* __restrict__ bb) {
    int i = blockIdx.x * blockDim.x + threadIdx.x;
    if (i < 49 * 49) {
        int q = i / 49, k = i % 49;
        float s = 0.0f;
        for (int e = 0; e < EMB; e++) s = fmaf(Wp[q * EMB + e], Wb[e * 49 + k], s);
        g_Wc[q * 52 + k] = s;
    } else if (i < 49 * 49 + NPK * 49) {
        int j = i - 49 * 49;
        int n = j / 49, k = j % 49;
        float s = bb[k];
        for (int e = 0; e < EMB; e++)
            s = fmaf(bp[e] + pe[n * EMB + e], Wb[e * 49 + k], s);
        g_bias[j] = s;
    } else if (i < 49 * 49 + NPK * 49 + 49 * 3) {
        int j = i - 49 * 49 - NPK * 49;
        g_Wc[(j / 3) * 52 + 49 + (j % 3)] = 0.0f;
    }
}

// ============================================================
// K1: sims + top-10 + transposed patches + byte-packed coords
// ============================================================
__global__ void __launch_bounds__(128) simtopk_kernel(const float* __restrict__ images) {
    __shared__ float swin_all[4][400];
    int wid = threadIdx.x >> 5, lane = threadIdx.x & 31;
    int unit = blockIdx.x * 4 + wid;
    float* swin = swin_all[wid];

    int p  = unit >> 5;
    int bc = unit & 31;
    int px = p / NGRID, py = p % NGRID;
    int x = px * 4, y = py * 4;
    int xb0 = x - 7; if (xb0 < 0) xb0 = 0;
    int yb0 = y - 7; if (yb0 < 0) yb0 = 0;
    int winW = x + 13 - xb0;
    int winH = y + 13 - yb0;

    const float* plane = images + (size_t)bc * (HH * WW);
    for (int t = lane; t < 400; t += 32)
        swin[t] = plane[(yb0 + t / 20) * WW + xb0 + (t % 20)];
    __syncwarp();

    int ry = y - yb0, rx = x - xb0;
    int r = lane >> 1, ox0 = (lane & 1) * 7;
    bool active = lane < 28;
    float acc[7];
    int flatbase;
    if (active) {
        #pragma unroll
        for (int o = 0; o < 7; o++) acc[o] = 0.0f;
        for (int a = 0; a < 7; a++) {
            float w[13];
            #pragma unroll
            for (int v = 0; v < 13; v++) w[v] = swin[(r + a) * 20 + ox0 + v];
            #pragma unroll
            for (int b = 0; b < 7; b++) {
                float rv = swin[(ry + a) * 20 + rx + b];
                #pragma unroll
                for (int o = 0; o < 7; o++) acc[o] = fmaf(w[o + b], rv, acc[o]);
            }
        }
        int maxr = winH - 7, maxc = winW - 7;
        #pragma unroll
        for (int o = 0; o < 7; o++)
            if (r > maxr || (ox0 + o) > maxc) acc[o] = -INFINITY;
        flatbase = r * LLEN + ox0;
    } else {
        #pragma unroll
        for (int o = 0; o < 7; o++) acc[o] = -INFINITY;
        flatbase = 1 << 20;
    }

    int xw0 = 0, xw1 = 0, xw2 = 0xC8C80000, yw0 = 0, yw1 = 0, yw2 = 0xC8C80000;

    for (int n = 0; n < NPK; n++) {
        float bv = -INFINITY; int bi = 0x7fffffff;
        #pragma unroll
        for (int o = 0; o < 7; o++) {
            float v = acc[o]; int ii = flatbase + o;
            if (v > bv || (v == bv && ii < bi)) { bv = v; bi = ii; }
        }
        #pragma unroll
        for (int off = 16; off > 0; off >>= 1) {
            float ov = __shfl_xor_sync(0xffffffffu, bv, off);
            int   oi = __shfl_xor_sync(0xffffffffu, bi, off);
            if (ov > bv || (ov == bv && oi < bi)) { bv = ov; bi = oi; }
        }
        if (active && bi >= flatbase && bi < flatbase + 7) acc[bi - flatbase] = -INFINITY;

        int oy = bi / LLEN, ox = bi - oy * LLEN;
        float* pout = g_patches + ((size_t)unit * NPK + n) * 49;
        pout[lane] = swin[(oy + lane % 7) * 20 + ox + lane / 7];
        if (lane < 17) {
            int q = lane + 32;
            pout[q] = swin[(oy + q % 7) * 20 + ox + q / 7];
        }
        if (lane == 0) {
            int xb = oy + xb0, yb = ox + yb0;   // bug kept: x from row off, y from col off
            int sh = (n & 3) * 8;
            if (n < 4)      { xw0 |= xb << sh; yw0 |= yb << sh; }
            else if (n < 8) { xw1 |= xb << sh; yw1 |= yb << sh; }
            else            { xw2 |= xb << sh; yw2 |= yb << sh; }
        }
    }
    if (lane == 0) {
        g_cp[unit * 2]     = make_int4(xw0, xw1, xw2, 0);
        g_cp[unit * 2 + 1] = make_int4(yw0, yw1, yw2, 0);
    }
}

// ============================================================
// K2: den[row] = patches[row] @ Wc + bias[row % 10], f32x2 packed
// ============================================================
__global__ void __launch_bounds__(128) gemm_kernel() {
    __shared__ float s_pat[128 * 49];
    __shared__ float s_Wc[49 * 52];
    __shared__ float s_bias[NPK * 49];
    int t = threadIdx.x;
    size_t base = (size_t)blockIdx.x * 128 * 49;
    for (int i = t; i < 128 * 49; i += 128) s_pat[i] = g_patches[base + i];
    for (int i = t; i < 49 * 52;  i += 128) s_Wc[i]  = g_Wc[i];
    for (int i = t; i < NPK * 49; i += 128) s_bias[i] = g_bias[i];
    __syncthreads();

    int grow = blockIdx.x * 128 + t;
    int n = grow % NPK;
    unsigned long long acc2[26];
    #pragma unroll
    for (int k2 = 0; k2 < 26; k2++) {
        float lo = (2 * k2     < 49) ? s_bias[n * 49 + 2 * k2]     : 0.0f;
        float hi = (2 * k2 + 1 < 49) ? s_bias[n * 49 + 2 * k2 + 1] : 0.0f;
        PACK2(acc2[k2], lo, hi);
    }
    for (int q = 0; q < 49; q++) {
        float pq = s_pat[t * 49 + q];
        unsigned long long pq2; PACK2(pq2, pq, pq);
        #pragma unroll
        for (int j = 0; j < 13; j++) {
            const ulonglong2* wp = (const ulonglong2*)&s_Wc[q * 52 + j * 4];
            ulonglong2 w = *wp;
            FMA2(acc2[2 * j],     pq2, w.x, acc2[2 * j]);
            FMA2(acc2[2 * j + 1], pq2, w.y, acc2[2 * j + 1]);
        }
    }
    __syncthreads();
    #pragma unroll
    for (int k2 = 0; k2 < 25; k2++) {
        float lo, hi; UNPK2(lo, hi, acc2[k2]);
        s_pat[t * 49 + 2 * k2] = lo;
        if (2 * k2 + 1 < 49) s_pat[t * 49 + 2 * k2 + 1] = hi;
    }
    __syncthreads();
    for (int i = t; i < 128 * 49; i += 128) g_den[base + i] = s_pat[i];
}

// ============================================================
// K3: per-pixel gather via REVERSE affine walk.
// forward step: v <- (v*fc + d)*rc, then counter inc at transposed loc.
// reverse: pre-count incs T, walk events backwards:
//   inc-undo: CNT--, refresh fc/rc/alpha
//   read:     B += (d*rc)*S; S *= alpha        (loads fully pipelined)
// final: v = v0*S + B
// ============================================================
__device__ __forceinline__ int inc_count_word(int xw, int yw, int cvec, int rvec) {
    unsigned m = __vcmpltu4(__vsub4(rvec, xw), SEV) &
                 __vcmpltu4(__vsub4(cvec, yw), SEV);
    return __popc(m & 0x01010101u);
}

__device__ __forceinline__ int inc_pos(int pidx, int cvec, int rvec) {
    int4 xq = g_cp[pidx * 2];
    int4 yq = g_cp[pidx * 2 + 1];
    return inc_count_word(xq.x, yq.x, cvec, rvec) +
           inc_count_word(xq.y, yq.y, cvec, rvec) +
           inc_count_word(xq.z, yq.z, cvec, rvec);
}

__device__ __forceinline__ void rev_read_word(int xw, int yw, int n0, int sbase,
                                              int cvec, int rvec, float rc, float al,
                                              float& S, float& B) {
    int xd = __vsub4(cvec, xw), yd = __vsub4(rvec, yw);
    unsigned m = __vcmpltu4(xd, SEV) & __vcmpltu4(yd, SEV);
    while (m) {
        int sh = (31 - __clz(m)) & 24;          // highest hit byte (largest n)
        int n = n0 + (sh >> 3);
        int didx = ((yd >> sh) & 7) * 7 + ((xd >> sh) & 7);
        float d = g_den[(size_t)(sbase + n) * 49 + didx];
        B = fmaf(d * rc, S, B);
        S *= al;
        m &= ~(0xFFu << sh);
    }
}

__device__ __forceinline__ void rev_read_pos(int pidx, int cvec, int rvec,
                                             float rc, float al, float& S, float& B) {
    int4 xq = g_cp[pidx * 2];
    int4 yq = g_cp[pidx * 2 + 1];
    int sbase = pidx * NPK;
    rev_read_word(xq.z, yq.z, 8, sbase, cvec, rvec, rc, al, S, B);
    rev_read_word(xq.y, yq.y, 4, sbase, cvec, rvec, rc, al, S, B);
    rev_read_word(xq.x, yq.x, 0, sbase, cvec, rvec, rc, al, S, B);
}

__device__ __forceinline__ void rev_mixed_word(int xw, int yw, int n0, int sbase,
                                               int cvec, int rvec,
                                               int& CNT, float& fc, float& rc, float& al,
                                               float& S, float& B,
                                               const float* __restrict__ s_rcp) {
    int xdR = __vsub4(cvec, xw), ydR = __vsub4(rvec, yw);
    unsigned mR = __vcmpltu4(xdR, SEV) & __vcmpltu4(ydR, SEV);
    unsigned mI = __vcmpltu4(__vsub4(rvec, xw), SEV) &
                  __vcmpltu4(__vsub4(cvec, yw), SEV);
    unsigned mo = mR | mI;
    while (mo) {
        int sh = (31 - __clz(mo)) & 24;
        if ((mI >> sh) & 1) {                    // undo this step's inc first
            CNT--; fc -= 1.0f; rc = s_rcp[CNT]; al = fc * rc;
        }
        if ((mR >> sh) & 1) {
            int n = n0 + (sh >> 3);
            int didx = ((ydR >> sh) & 7) * 7 + ((xdR >> sh) & 7);
            float d = g_den[(size_t)(sbase + n) * 49 + didx];
            B = fmaf(d * rc, S, B);
            S *= al;
        }
        mo &= ~(0xFFu << sh);
    }
}

__device__ __forceinline__ void rev_mixed_pos(int pidx, int cvec, int rvec,
                                              int& CNT, float& fc, float& rc, float& al,
                                              float& S, float& B,
                                              const float* __restrict__ s_rcp) {
    int4 xq = g_cp[pidx * 2];
    int4 yq = g_cp[pidx * 2 + 1];
    int sbase = pidx * NPK;
    rev_mixed_word(xq.z, yq.z, 8, sbase, cvec, rvec, CNT, fc, rc, al, S, B, s_rcp);
    rev_mixed_word(xq.y, yq.y, 4, sbase, cvec, rvec, CNT, fc, rc, al, S, B, s_rcp);
    rev_mixed_word(xq.x, yq.x, 0, sbase, cvec, rvec, CNT, fc, rc, al, S, B, s_rcp);
}

__global__ void __launch_bounds__(256) gather_kernel(const float* __restrict__ images,
                                                     float* __restrict__ out) {
    __shared__ float s_rcp[512];
    {
        int t = threadIdx.y * 32 + threadIdx.x;
        for (int i = t; i < 512; i += 256) s_rcp[i] = __frcp_rn((float)(i + 1));
    }
    __syncthreads();

    int bc  = threadIdx.x;                       // lane = plane -> uniform (r,c) per warp
    int pix = blockIdx.x * 8 + threadIdx.y;
    int r = pix / WW, c = pix % WW;

    float v0 = images[(size_t)bc * (HH * WW) + pix];
    float v = v0;

    int lr = (r <= 19) ? 0 : ((r - 9) >> 2);
    int hr = (r + 7) >> 2; if (hr > 35) hr = 35;
    int lc = (c <= 19) ? 0 : ((c - 9) >> 2);
    int hc = (c + 7) >> 2; if (hc > 35) hc = 35;

    if (lr <= hr && lc <= hc) {
        int cvec = c * 0x01010101, rvec = r * 0x01010101;
        float S = 1.0f, B = 0.0f;

        if (hc < lr) {
            // all reads happen before any inc: c = 1 throughout
            for (int px = hc; px >= lc; --px) {
                int pbase = (px * NGRID + hr) * NBC + bc;
                for (int py = hr; py >= lr; --py, pbase -= NBC)
                    rev_read_pos(pbase, cvec, rvec, 0.5f, 0.5f, S, B);
            }
        } else if (hr < lc) {
            // all incs before all reads: constant c = 1 + T
            int T = 0;
            for (int px = lr; px <= hr; ++px) {
                int pbase = (px * NGRID + lc) * NBC + bc;
                for (int py = lc; py <= hc; ++py, pbase += NBC)
                    T += inc_pos(pbase, cvec, rvec);
            }
            float fc = (float)(1 + T);
            float rc = s_rcp[1 + T];
            float al = fc * rc;
            for (int px = hc; px >= lc; --px) {
                int pbase = (px * NGRID + hr) * NBC + bc;
                for (int py = hr; py >= lr; --py, pbase -= NBC)
                    rev_read_pos(pbase, cvec, rvec, rc, al, S, B);
            }
        } else {
            // general: pre-count incs, reverse merged walk
            int T = 0;
            for (int px = lr; px <= hr; ++px) {
                int pbase = (px * NGRID + lc) * NBC + bc;
                for (int py = lc; py <= hc; ++py, pbase += NBC)
                    T += inc_pos(pbase, cvec, rvec);
            }
            int CNT = 1 + T;
            float fc = (float)CNT, rc = s_rcp[CNT], al = fc * rc;

            int pmin = min(lr, lc), pmax = max(hr, hc);
            for (int px = pmax; px >= pmin; --px) {
                bool cR = (px >= lc) & (px <= hc);
                bool cI = (px >= lr) & (px <= hr);
                if (cR & cI) {
                    int pbase = (px * NGRID + pmax) * NBC + bc;
                    for (int py = pmax; py >= pmin; --py, pbase -= NBC) {
                        bool pR = (py >= lr) & (py <= hr);
                        bool pC = (py >= lc) & (py <= hc);
                        if (pR & pC)      rev_mixed_pos(pbase, cvec, rvec, CNT, fc, rc, al, S, B, s_rcp);
                        else if (pR)      rev_read_pos(pbase, cvec, rvec, rc, al, S, B);
                        else if (pC) {
                            int k = inc_pos(pbase, cvec, rvec);
                            CNT -= k; fc -= (float)k; rc = s_rcp[CNT]; al = fc * rc;
                        }
                    }
                } else if (cR) {
                    int pbase = (px * NGRID + hr) * NBC + bc;
                    for (int py = hr; py >= lr; --py, pbase -= NBC)
                        rev_read_pos(pbase, cvec, rvec, rc, al, S, B);
                } else if (cI) {
                    int k = 0;
                    int pbase = (px * NGRID + lc) * NBC + bc;
                    for (int py = lc; py <= hc; ++py, pbase += NBC)
                        k += inc_pos(pbase, cvec, rvec);
                    CNT -= k; fc -= (float)k; rc = s_rcp[CNT]; al = fc * rc;
                }
            }
        }
        v = fmaf(v0, S, B);
    }

    out[(size_t)bc * (HH * WW) + pix] = v;
}

// ============================================================
extern "C" void kernel_launch(void* const* d_in, const int* in_sizes, int n_in,
                              void* d_out, int out_size) {
    const float* images = (const float*)d_in[0];
    const float* Wp = (const float*)d_in[1];
    const float* bp = (const float*)d_in[2];
    const float* pe = (const float*)d_in[3];
    const float* Wb = (const float*)d_in[4];
    const float* bb = (const float*)d_in[5];
    float* out = (float*)d_out;

    int prep_items = 49 * 49 + NPK * 49 + 49 * 3;
    prep_kernel<<<(prep_items + 127) / 128, 128>>>(Wp, bp, pe, Wb, bb);
    simtopk_kernel<<<NUNIT / 4, 128>>>(images);
    gemm_kernel<<<NROW / 128, 128>>>();

    dim3 gg((HH * WW) / 8);
    dim3 bl(32, 8);
    gather_kernel<<<gg, bl>>>(images, out);
}

// round 7
// speedup vs baseline: 1.6643x; 1.6643x over previous
#include <cuda_runtime.h>
#include <math.h>

// ---- problem constants ----
#define NPK   10
#define LLEN  14
#define EMB   128
#define HH    160
#define WW    160
#define NBC   32
#define NGRID 36
#define NPOS  (NGRID*NGRID)
#define NUNIT (NPOS*NBC)    // 41472
#define NROW  (NUNIT*NPK)   // 414720
#define SEV   0x07070707

// ---- static scratch ----
__device__ float g_patches[(size_t)NROW * 49];
__device__ float g_den[(size_t)NROW * 49];
__device__ int4  g_cp[NUNIT * 2];   // [2u]=x-bytes(10+2 pad 0xC8), [2u+1]=y-bytes
__device__ float g_Wc[49 * 52];
__device__ float g_bias[NPK * 49];

// ============================================================
// K0: fold projections
// ============================================================
__global__ void prep_kernel(const float* __restrict__ Wp, const float* __restrict__ bp,
                            const float* __restrict__ pe, const float* __restrict__ Wb,
                            const float* __restrict__ bb) {
    int i = blockIdx.x * blockDim.x + threadIdx.x;
    if (i < 49 * 49) {
        int q = i / 49, k = i % 49;
        float s = 0.0f;
        for (int e = 0; e < EMB; e++) s = fmaf(Wp[q * EMB + e], Wb[e * 49 + k], s);
        g_Wc[q * 52 + k] = s;
    } else if (i < 49 * 49 + NPK * 49) {
        int j = i - 49 * 49;
        int n = j / 49, k = j % 49;
        float s = bb[k];
        for (int e = 0; e < EMB; e++)
            s = fmaf(bp[e] + pe[n * EMB + e], Wb[e * 49 + k], s);
        g_bias[j] = s;
    } else if (i < 49 * 49 + NPK * 49 + 49 * 3) {
        int j = i - 49 * 49 - NPK * 49;
        g_Wc[(j / 3) * 52 + 49 + (j % 3)] = 0.0f;
    }
}

// ============================================================
// K1: sims + top-10 + transposed patches + byte-packed coords
// ============================================================
__global__ void __launch_bounds__(128) simtopk_kernel(const float* __restrict__ images) {
    __shared__ float swin_all[4][400];
    int wid = threadIdx.x >> 5, lane = threadIdx.x & 31;
    int unit = blockIdx.x * 4 + wid;
    float* swin = swin_all[wid];

    int p  = unit >> 5;
    int bc = unit & 31;
    int px = p / NGRID, py = p % NGRID;
    int x = px * 4, y = py * 4;
    int xb0 = x - 7; if (xb0 < 0) xb0 = 0;
    int yb0 = y - 7; if (yb0 < 0) yb0 = 0;
    int winW = x + 13 - xb0;
    int winH = y + 13 - yb0;

    const float* plane = images + (size_t)bc * (HH * WW);
    for (int t = lane; t < 400; t += 32)
        swin[t] = plane[(yb0 + t / 20) * WW + xb0 + (t % 20)];
    __syncwarp();

    int ry = y - yb0, rx = x - xb0;
    int r = lane >> 1, ox0 = (lane & 1) * 7;
    bool active = lane < 28;
    float acc[7];
    int flatbase;
    if (active) {
        #pragma unroll
        for (int o = 0; o < 7; o++) acc[o] = 0.0f;
        for (int a = 0; a < 7; a++) {
            float w[13];
            #pragma unroll
            for (int v = 0; v < 13; v++) w[v] = swin[(r + a) * 20 + ox0 + v];
            #pragma unroll
            for (int b = 0; b < 7; b++) {
                float rv = swin[(ry + a) * 20 + rx + b];
                #pragma unroll
                for (int o = 0; o < 7; o++) acc[o] = fmaf(w[o + b], rv, acc[o]);
            }
        }
        int maxr = winH - 7, maxc = winW - 7;
        #pragma unroll
        for (int o = 0; o < 7; o++)
            if (r > maxr || (ox0 + o) > maxc) acc[o] = -INFINITY;
        flatbase = r * LLEN + ox0;
    } else {
        #pragma unroll
        for (int o = 0; o < 7; o++) acc[o] = -INFINITY;
        flatbase = 1 << 20;
    }

    int xw0 = 0, xw1 = 0, xw2 = 0xC8C80000, yw0 = 0, yw1 = 0, yw2 = 0xC8C80000;

    for (int n = 0; n < NPK; n++) {
        float bv = -INFINITY; int bi = 0x7fffffff;
        #pragma unroll
        for (int o = 0; o < 7; o++) {
            float v = acc[o]; int ii = flatbase + o;
            if (v > bv || (v == bv && ii < bi)) { bv = v; bi = ii; }
        }
        #pragma unroll
        for (int off = 16; off > 0; off >>= 1) {
            float ov = __shfl_xor_sync(0xffffffffu, bv, off);
            int   oi = __shfl_xor_sync(0xffffffffu, bi, off);
            if (ov > bv || (ov == bv && oi < bi)) { bv = ov; bi = oi; }
        }
        if (active && bi >= flatbase && bi < flatbase + 7) acc[bi - flatbase] = -INFINITY;

        int oy = bi / LLEN, ox = bi - oy * LLEN;
        float* pout = g_patches + ((size_t)unit * NPK + n) * 49;
        pout[lane] = swin[(oy + lane % 7) * 20 + ox + lane / 7];
        if (lane < 17) {
            int q = lane + 32;
            pout[q] = swin[(oy + q % 7) * 20 + ox + q / 7];
        }
        if (lane == 0) {
            int xb = oy + xb0, yb = ox + yb0;   // bug kept: x from row off, y from col off
            int sh = (n & 3) * 8;
            if (n < 4)      { xw0 |= xb << sh; yw0 |= yb << sh; }
            else if (n < 8) { xw1 |= xb << sh; yw1 |= yb << sh; }
            else            { xw2 |= xb << sh; yw2 |= yb << sh; }
        }
    }
    if (lane == 0) {
        g_cp[unit * 2]     = make_int4(xw0, xw1, xw2, 0);
        g_cp[unit * 2 + 1] = make_int4(yw0, yw1, yw2, 0);
    }
}

// ============================================================
// K2: den[row] = patches[row] @ Wc + bias[row % 10]  (scalar, R5)
// ============================================================
__global__ void __launch_bounds__(128) gemm_kernel() {
    __shared__ float s_pat[128 * 49];
    __shared__ float s_Wc[49 * 52];
    __shared__ float s_bias[NPK * 49];
    int t = threadIdx.x;
    size_t base = (size_t)blockIdx.x * 128 * 49;
    for (int i = t; i < 128 * 49; i += 128) s_pat[i] = g_patches[base + i];
    for (int i = t; i < 49 * 52;  i += 128) s_Wc[i]  = g_Wc[i];
    for (int i = t; i < NPK * 49; i += 128) s_bias[i] = g_bias[i];
    __syncthreads();

    int grow = blockIdx.x * 128 + t;
    int n = grow % NPK;
    float acc[52];
    #pragma unroll
    for (int k = 0; k < 52; k++) acc[k] = (k < 49) ? s_bias[n * 49 + k] : 0.0f;
    for (int q = 0; q < 49; q++) {
        float pq = s_pat[t * 49 + q];
        #pragma unroll
        for (int k4 = 0; k4 < 13; k4++) {
            float4 w = *(const float4*)&s_Wc[q * 52 + k4 * 4];
            acc[k4 * 4 + 0] = fmaf(pq, w.x, acc[k4 * 4 + 0]);
            acc[k4 * 4 + 1] = fmaf(pq, w.y, acc[k4 * 4 + 1]);
            acc[k4 * 4 + 2] = fmaf(pq, w.z, acc[k4 * 4 + 2]);
            acc[k4 * 4 + 3] = fmaf(pq, w.w, acc[k4 * 4 + 3]);
        }
    }
    __syncthreads();
    #pragma unroll
    for (int k = 0; k < 49; k++) s_pat[t * 49 + k] = acc[k];
    __syncthreads();
    for (int i = t; i < 128 * 49; i += 128) g_den[base + i] = s_pat[i];
}

// ============================================================
// K3: per-pixel gather, FORWARD order, affine (W,B) accumulation:
//   read at counter c : B = fma(d, W, B);  W *= (c+1)/c
//   inc  c -> c+1     : W *= c/(c+1)       (k incs: W *= c/(c+k))
//   final             : v = (v0 + B) * frcp(W * c_final)
// d loads enter only as FMA addends -> fully pipelined.
// ============================================================
__device__ __forceinline__ int inc_count_word(int xw, int yw, int cvec, int rvec) {
    unsigned m = __vcmpltu4(__vsub4(rvec, xw), SEV) &
                 __vcmpltu4(__vsub4(cvec, yw), SEV);
    return __popc(m & 0x01010101u);
}

__device__ __forceinline__ int inc_pos(int pidx, int cvec, int rvec) {
    int4 xq = g_cp[pidx * 2];
    int4 yq = g_cp[pidx * 2 + 1];
    return inc_count_word(xq.x, yq.x, cvec, rvec) +
           inc_count_word(xq.y, yq.y, cvec, rvec) +
           inc_count_word(xq.z, yq.z, cvec, rvec);
}

__device__ __forceinline__ void read_word(int xw, int yw, int n0, int sbase,
                                          int cvec, int rvec, float bw,
                                          float& W, float& B) {
    int xd = __vsub4(cvec, xw), yd = __vsub4(rvec, yw);
    unsigned m = __vcmpltu4(xd, SEV) & __vcmpltu4(yd, SEV);
    while (m) {
        int sh = __ffs(m) - 1;                 // byte-aligned
        int n = n0 + (sh >> 3);
        int didx = ((yd >> sh) & 7) * 7 + ((xd >> sh) & 7);
        float d = g_den[(size_t)(sbase + n) * 49 + didx];
        B = fmaf(d, W, B);
        W *= bw;
        m &= ~(0xFFu << sh);
    }
}

__device__ __forceinline__ void read_pos(int pidx, int cvec, int rvec,
                                         float bw, float& W, float& B) {
    int4 xq = g_cp[pidx * 2];
    int4 yq = g_cp[pidx * 2 + 1];
    int sbase = pidx * NPK;
    read_word(xq.x, yq.x, 0, sbase, cvec, rvec, bw, W, B);
    read_word(xq.y, yq.y, 4, sbase, cvec, rvec, bw, W, B);
    read_word(xq.z, yq.z, 8, sbase, cvec, rvec, bw, W, B);
}

__device__ __forceinline__ void mixed_word(int xw, int yw, int n0, int sbase,
                                           int cvec, int rvec,
                                           int& cnt, float& bw, float& W, float& B,
                                           const float* __restrict__ s_rcp) {
    int xdR = __vsub4(cvec, xw), ydR = __vsub4(rvec, yw);
    unsigned mR = __vcmpltu4(xdR, SEV) & __vcmpltu4(ydR, SEV);
    unsigned mI = __vcmpltu4(__vsub4(rvec, xw), SEV) &
                  __vcmpltu4(__vsub4(cvec, yw), SEV);
    unsigned mo = mR | mI;
    while (mo) {
        int sh = __ffs(mo) - 1;
        if ((mR >> sh) & 1) {                  // read first (pre-inc counter)
            int n = n0 + (sh >> 3);
            int didx = ((ydR >> sh) & 7) * 7 + ((xdR >> sh) & 7);
            float d = g_den[(size_t)(sbase + n) * 49 + didx];
            B = fmaf(d, W, B);
            W *= bw;
        }
        if ((mI >> sh) & 1) {
            W *= (1.0f - s_rcp[cnt + 1]);      // c/(c+1)
            cnt++;
            bw = 1.0f + s_rcp[cnt];            // (c+1)/c
        }
        mo &= ~(0xFFu << sh);
    }
}

__device__ __forceinline__ void mixed_pos(int pidx, int cvec, int rvec,
                                          int& cnt, float& bw, float& W, float& B,
                                          const float* __restrict__ s_rcp) {
    int4 xq = g_cp[pidx * 2];
    int4 yq = g_cp[pidx * 2 + 1];
    int sbase = pidx * NPK;
    mixed_word(xq.x, yq.x, 0, sbase, cvec, rvec, cnt, bw, W, B, s_rcp);
    mixed_word(xq.y, yq.y, 4, sbase, cvec, rvec, cnt, bw, W, B, s_rcp);
    mixed_word(xq.z, yq.z, 8, sbase, cvec, rvec, cnt, bw, W, B, s_rcp);
}

__global__ void __launch_bounds__(256) gather_kernel(const float* __restrict__ images,
                                                     float* __restrict__ out) {
    __shared__ float s_rcp[512];
    {
        int t = threadIdx.y * 32 + threadIdx.x;
        for (int i = t; i < 512; i += 256) s_rcp[i] = __frcp_rn((float)i);  // s_rcp[c] = 1/c
    }
    __syncthreads();

    int bc  = threadIdx.x;                       // lane = plane -> uniform (r,c) per warp
    int pix = blockIdx.x * 8 + threadIdx.y;
    int r = pix / WW, c = pix % WW;

    float v0 = images[(size_t)bc * (HH * WW) + pix];
    float v = v0;

    int lr = (r <= 19) ? 0 : ((r - 9) >> 2);
    int hr = (r + 7) >> 2; if (hr > 35) hr = 35;
    int lc = (c <= 19) ? 0 : ((c - 9) >> 2);
    int hc = (c + 7) >> 2; if (hc > 35) hc = 35;

    if (lr <= hr && lc <= hc) {
        int cvec = c * 0x01010101, rvec = r * 0x01010101;
        float W = 1.0f, B = 0.0f;
        int cnt = 1;

        if (hc < lr) {
            // all reads before any inc: counter = 1, bw = 2
            for (int px = lc; px <= hc; ++px) {
                int pbase = (px * NGRID + lr) * NBC + bc;
                for (int py = lr; py <= hr; ++py, pbase += NBC)
                    read_pos(pbase, cvec, rvec, 2.0f, W, B);
            }
        } else if (hr < lc) {
            // all incs before all reads: counter constant 1+T
            int T = 0;
            for (int px = lr; px <= hr; ++px) {
                int pbase = (px * NGRID + lc) * NBC + bc;
                for (int py = lc; py <= hc; ++py, pbase += NBC)
                    T += inc_pos(pbase, cvec, rvec);
            }
            cnt = 1 + T;
            W = s_rcp[cnt];                      // (1/c) * RPinv(=1)
            float bw = 1.0f + s_rcp[cnt];
            for (int px = lc; px <= hc; ++px) {
                int pbase = (px * NGRID + lr) * NBC + bc;
                for (int py = lr; py <= hr; ++py, pbase += NBC)
                    read_pos(pbase, cvec, rvec, bw, W, B);
            }
        } else {
            // general merged walk in step order
            float bw = 2.0f;
            int pmin = min(lr, lc), pmax = max(hr, hc);
            for (int px = pmin; px <= pmax; ++px) {
                bool cR = (px >= lc) & (px <= hc);
                bool cI = (px >= lr) & (px <= hr);
                if (cR & cI) {
                    int pbase = (px * NGRID + pmin) * NBC + bc;
                    for (int py = pmin; py <= pmax; ++py, pbase += NBC) {
                        bool pR = (py >= lr) & (py <= hr);
                        bool pC = (py >= lc) & (py <= hc);
                        if (pR & pC)      mixed_pos(pbase, cvec, rvec, cnt, bw, W, B, s_rcp);
                        else if (pR)      read_pos(pbase, cvec, rvec, bw, W, B);
                        else if (pC) {
                            int k = inc_pos(pbase, cvec, rvec);
                            if (k) {
                                W *= (float)cnt * s_rcp[cnt + k];   // c/(c+k)
                                cnt += k;
                                bw = 1.0f + s_rcp[cnt];
                            }
                        }
                    }
                } else if (cR) {
                    int pbase = (px * NGRID + lr) * NBC + bc;
                    for (int py = lr; py <= hr; ++py, pbase += NBC)
                        read_pos(pbase, cvec, rvec, bw, W, B);
                } else if (cI) {
                    int k = 0;
                    int pbase = (px * NGRID + lc) * NBC + bc;
                    for (int py = lc; py <= hc; ++py, pbase += NBC)
                        k += inc_pos(pbase, cvec, rvec);
                    if (k) {
                        W *= (float)cnt * s_rcp[cnt + k];
                        cnt += k;
                        bw = 1.0f + s_rcp[cnt];
                    }
                }
            }
        }
        // v = (v0 + B) * P,  P = 1/(W * c_final)
        v = (v0 + B) * __frcp_rn(W * (float)cnt);
    }

    out[(size_t)bc * (HH * WW) + pix] = v;
}

// ============================================================
extern "C" void kernel_launch(void* const* d_in, const int* in_sizes, int n_in,
                              void* d_out, int out_size) {
    const float* images = (const float*)d_in[0];
    const float* Wp = (const float*)d_in[1];
    const float* bp = (const float*)d_in[2];
    const float* pe = (const float*)d_in[3];
    const float* Wb = (const float*)d_in[4];
    const float* bb = (const float*)d_in[5];
    float* out = (float*)d_out;

    int prep_items = 49 * 49 + NPK * 49 + 49 * 3;
    prep_kernel<<<(prep_items + 127) / 128, 128>>>(Wp, bp, pe, Wb, bb);
    simtopk_kernel<<<NUNIT / 4, 128>>>(images);
    gemm_kernel<<<NROW / 128, 128>>>();

    dim3 gg((HH * WW) / 8);
    dim3 bl(32, 8);
    gather_kernel<<<gg, bl>>>(images, out);
}

// round 8
// speedup vs baseline: 1.8223x; 1.0949x over previous
#include <cuda_runtime.h>
#include <math.h>

// ---- problem constants ----
#define NPK   10
#define LLEN  14
#define EMB   128
#define HH    160
#define WW    160
#define NBC   32
#define NGRID 36
#define NPOS  (NGRID*NGRID)
#define NUNIT (NPOS*NBC)    // 41472
#define NROW  (NUNIT*NPK)   // 414720
#define SEV   0x07070707

// ---- static scratch ----
__device__ float g_patches[(size_t)NROW * 49];
__device__ float g_den[(size_t)NROW * 49];
__device__ int4  g_cp[NUNIT * 2];   // [2u]=x-bytes(10+2 pad 0xC8), [2u+1]=y-bytes
__device__ float g_Wc[49 * 52];
__device__ float g_bias[NPK * 49];

// ============================================================
// K0: fold projections
// ============================================================
__global__ void prep_kernel(const float* __restrict__ Wp, const float* __restrict__ bp,
                            const float* __restrict__ pe, const float* __restrict__ Wb,
                            const float* __restrict__ bb) {
    int i = blockIdx.x * blockDim.x + threadIdx.x;
    if (i < 49 * 49) {
        int q = i / 49, k = i % 49;
        float s = 0.0f;
        for (int e = 0; e < EMB; e++) s = fmaf(Wp[q * EMB + e], Wb[e * 49 + k], s);
        g_Wc[q * 52 + k] = s;
    } else if (i < 49 * 49 + NPK * 49) {
        int j = i - 49 * 49;
        int n = j / 49, k = j % 49;
        float s = bb[k];
        for (int e = 0; e < EMB; e++)
            s = fmaf(bp[e] + pe[n * EMB + e], Wb[e * 49 + k], s);
        g_bias[j] = s;
    } else if (i < 49 * 49 + NPK * 49 + 49 * 3) {
        int j = i - 49 * 49 - NPK * 49;
        g_Wc[(j / 3) * 52 + 49 + (j % 3)] = 0.0f;
    }
}

// ============================================================
// K1: sims + top-10 (REDUX reductions, lax.top_k tie-break) +
//     transposed patches + byte-packed coords
// ============================================================
__global__ void __launch_bounds__(128) simtopk_kernel(const float* __restrict__ images) {
    __shared__ float swin_all[4][400];
    int wid = threadIdx.x >> 5, lane = threadIdx.x & 31;
    int unit = blockIdx.x * 4 + wid;
    float* swin = swin_all[wid];

    int p  = unit >> 5;
    int bc = unit & 31;
    int px = p / NGRID, py = p % NGRID;
    int x = px * 4, y = py * 4;
    int xb0 = x - 7; if (xb0 < 0) xb0 = 0;
    int yb0 = y - 7; if (yb0 < 0) yb0 = 0;
    int winW = x + 13 - xb0;
    int winH = y + 13 - yb0;

    const float* plane = images + (size_t)bc * (HH * WW);
    for (int t = lane; t < 400; t += 32)
        swin[t] = plane[(yb0 + t / 20) * WW + xb0 + (t % 20)];
    __syncwarp();

    int ry = y - yb0, rx = x - xb0;
    int r = lane >> 1, ox0 = (lane & 1) * 7;
    bool active = lane < 28;
    float acc[7];
    int flatbase;
    if (active) {
        #pragma unroll
        for (int o = 0; o < 7; o++) acc[o] = 0.0f;
        for (int a = 0; a < 7; a++) {
            float w[13];
            #pragma unroll
            for (int v = 0; v < 13; v++) w[v] = swin[(r + a) * 20 + ox0 + v];
            #pragma unroll
            for (int b = 0; b < 7; b++) {
                float rv = swin[(ry + a) * 20 + rx + b];
                #pragma unroll
                for (int o = 0; o < 7; o++) acc[o] = fmaf(w[o + b], rv, acc[o]);
            }
        }
        int maxr = winH - 7, maxc = winW - 7;
        #pragma unroll
        for (int o = 0; o < 7; o++)
            if (r > maxr || (ox0 + o) > maxc) acc[o] = -INFINITY;
        flatbase = r * LLEN + ox0;
    } else {
        #pragma unroll
        for (int o = 0; o < 7; o++) acc[o] = -INFINITY;
        flatbase = 1 << 20;
    }

    int lane_m7 = lane % 7, lane_d7 = lane / 7;
    int q32_m7 = (lane + 32) % 7, q32_d7 = (lane + 32) / 7;

    int xw0 = 0, xw1 = 0, xw2 = 0xC8C80000, yw0 = 0, yw1 = 0, yw2 = 0xC8C80000;

    for (int n = 0; n < NPK; n++) {
        // lane-local best (strict > keeps lowest o -> lowest flat index)
        float bv = acc[0]; int bo = 0;
        #pragma unroll
        for (int o = 1; o < 7; o++)
            if (acc[o] > bv) { bv = acc[o]; bo = o; }
        // order-preserving uint transform, then single-instruction reductions
        unsigned ub = __float_as_uint(bv);
        ub ^= (unsigned)(((int)ub >> 31)) | 0x80000000u;
        unsigned wmax = __reduce_max_sync(0xffffffffu, ub);
        int cand = (ub == wmax) ? (flatbase + bo) : 0x7fffffff;
        int bi = __reduce_min_sync(0xffffffffu, cand);

        if (active && bi >= flatbase && bi < flatbase + 7) acc[bi - flatbase] = -INFINITY;

        int oy = bi / LLEN, ox = bi - oy * LLEN;
        float* pout = g_patches + ((size_t)unit * NPK + n) * 49;
        pout[lane] = swin[(oy + lane_m7) * 20 + ox + lane_d7];
        if (lane < 17)
            pout[lane + 32] = swin[(oy + q32_m7) * 20 + ox + q32_d7];
        if (lane == 0) {
            int xb = oy + xb0, yb = ox + yb0;   // bug kept: x from row off, y from col off
            int sh = (n & 3) * 8;
            if (n < 4)      { xw0 |= xb << sh; yw0 |= yb << sh; }
            else if (n < 8) { xw1 |= xb << sh; yw1 |= yb << sh; }
            else            { xw2 |= xb << sh; yw2 |= yb << sh; }
        }
    }
    if (lane == 0) {
        g_cp[unit * 2]     = make_int4(xw0, xw1, xw2, 0);
        g_cp[unit * 2 + 1] = make_int4(yw0, yw1, yw2, 0);
    }
}

// ============================================================
// K2: den[row] = patches[row] @ Wc + bias[row % 10]
// 12 x float4 + 1 scalar (exactly 49 cols, no pad compute)
// ============================================================
__global__ void __launch_bounds__(128) gemm_kernel() {
    __shared__ float s_pat[128 * 49];
    __shared__ float s_Wc[49 * 52];
    __shared__ float s_bias[NPK * 49];
    int t = threadIdx.x;
    size_t base = (size_t)blockIdx.x * 128 * 49;
    for (int i = t; i < 128 * 49; i += 128) s_pat[i] = g_patches[base + i];
    for (int i = t; i < 49 * 52;  i += 128) s_Wc[i]  = g_Wc[i];
    for (int i = t; i < NPK * 49; i += 128) s_bias[i] = g_bias[i];
    __syncthreads();

    int grow = blockIdx.x * 128 + t;
    int n = grow % NPK;
    float acc[49];
    #pragma unroll
    for (int k = 0; k < 49; k++) acc[k] = s_bias[n * 49 + k];
    for (int q = 0; q < 49; q++) {
        float pq = s_pat[t * 49 + q];
        #pragma unroll
        for (int k4 = 0; k4 < 12; k4++) {
            float4 w = *(const float4*)&s_Wc[q * 52 + k4 * 4];
            acc[k4 * 4 + 0] = fmaf(pq, w.x, acc[k4 * 4 + 0]);
            acc[k4 * 4 + 1] = fmaf(pq, w.y, acc[k4 * 4 + 1]);
            acc[k4 * 4 + 2] = fmaf(pq, w.z, acc[k4 * 4 + 2]);
            acc[k4 * 4 + 3] = fmaf(pq, w.w, acc[k4 * 4 + 3]);
        }
        acc[48] = fmaf(pq, s_Wc[q * 52 + 48], acc[48]);
    }
    __syncthreads();
    #pragma unroll
    for (int k = 0; k < 49; k++) s_pat[t * 49 + k] = acc[k];
    __syncthreads();
    for (int i = t; i < 128 * 49; i += 128) g_den[base + i] = s_pat[i];
}

// ============================================================
// K3: per-pixel gather (R7, unchanged): forward order, affine (W,B):
//   read at counter c : B = fma(d, W, B);  W *= (c+1)/c
//   inc  c -> c+1     : W *= c/(c+1)       (k incs: W *= c/(c+k))
//   final             : v = (v0 + B) * frcp(W * c_final)
// ============================================================
__device__ __forceinline__ int inc_count_word(int xw, int yw, int cvec, int rvec) {
    unsigned m = __vcmpltu4(__vsub4(rvec, xw), SEV) &
                 __vcmpltu4(__vsub4(cvec, yw), SEV);
    return __popc(m & 0x01010101u);
}

__device__ __forceinline__ int inc_pos(int pidx, int cvec, int rvec) {
    int4 xq = g_cp[pidx * 2];
    int4 yq = g_cp[pidx * 2 + 1];
    return inc_count_word(xq.x, yq.x, cvec, rvec) +
           inc_count_word(xq.y, yq.y, cvec, rvec) +
           inc_count_word(xq.z, yq.z, cvec, rvec);
}

__device__ __forceinline__ void read_word(int xw, int yw, int n0, int sbase,
                                          int cvec, int rvec, float bw,
                                          float& W, float& B) {
    int xd = __vsub4(cvec, xw), yd = __vsub4(rvec, yw);
    unsigned m = __vcmpltu4(xd, SEV) & __vcmpltu4(yd, SEV);
    while (m) {
        int sh = __ffs(m) - 1;
        int n = n0 + (sh >> 3);
        int didx = ((yd >> sh) & 7) * 7 + ((xd >> sh) & 7);
        float d = g_den[(size_t)(sbase + n) * 49 + didx];
        B = fmaf(d, W, B);
        W *= bw;
        m &= ~(0xFFu << sh);
    }
}

__device__ __forceinline__ void read_pos(int pidx, int cvec, int rvec,
                                         float bw, float& W, float& B) {
    int4 xq = g_cp[pidx * 2];
    int4 yq = g_cp[pidx * 2 + 1];
    int sbase = pidx * NPK;
    read_word(xq.x, yq.x, 0, sbase, cvec, rvec, bw, W, B);
    read_word(xq.y, yq.y, 4, sbase, cvec, rvec, bw, W, B);
    read_word(xq.z, yq.z, 8, sbase, cvec, rvec, bw, W, B);
}

__device__ __forceinline__ void mixed_word(int xw, int yw, int n0, int sbase,
                                           int cvec, int rvec,
                                           int& cnt, float& bw, float& W, float& B,
                                           const float* __restrict__ s_rcp) {
    int xdR = __vsub4(cvec, xw), ydR = __vsub4(rvec, yw);
    unsigned mR = __vcmpltu4(xdR, SEV) & __vcmpltu4(ydR, SEV);
    unsigned mI = __vcmpltu4(__vsub4(rvec, xw), SEV) &
                  __vcmpltu4(__vsub4(cvec, yw), SEV);
    unsigned mo = mR | mI;
    while (mo) {
        int sh = __ffs(mo) - 1;
        if ((mR >> sh) & 1) {
            int n = n0 + (sh >> 3);
            int didx = ((ydR >> sh) & 7) * 7 + ((xdR >> sh) & 7);
            float d = g_den[(size_t)(sbase + n) * 49 + didx];
            B = fmaf(d, W, B);
            W *= bw;
        }
        if ((mI >> sh) & 1) {
            W *= (1.0f - s_rcp[cnt + 1]);
            cnt++;
            bw = 1.0f + s_rcp[cnt];
        }
        mo &= ~(0xFFu << sh);
    }
}

__device__ __forceinline__ void mixed_pos(int pidx, int cvec, int rvec,
                                          int& cnt, float& bw, float& W, float& B,
                                          const float* __restrict__ s_rcp) {
    int4 xq = g_cp[pidx * 2];
    int4 yq = g_cp[pidx * 2 + 1];
    int sbase = pidx * NPK;
    mixed_word(xq.x, yq.x, 0, sbase, cvec, rvec, cnt, bw, W, B, s_rcp);
    mixed_word(xq.y, yq.y, 4, sbase, cvec, rvec, cnt, bw, W, B, s_rcp);
    mixed_word(xq.z, yq.z, 8, sbase, cvec, rvec, cnt, bw, W, B, s_rcp);
}

__global__ void __launch_bounds__(256) gather_kernel(const float* __restrict__ images,
                                                     float* __restrict__ out) {
    __shared__ float s_rcp[512];
    {
        int t = threadIdx.y * 32 + threadIdx.x;
        for (int i = t; i < 512; i += 256) s_rcp[i] = __frcp_rn((float)i);  // s_rcp[c] = 1/c
    }
    __syncthreads();

    int bc  = threadIdx.x;
    int pix = blockIdx.x * 8 + threadIdx.y;
    int r = pix / WW, c = pix % WW;

    float v0 = images[(size_t)bc * (HH * WW) + pix];
    float v = v0;

    int lr = (r <= 19) ? 0 : ((r - 9) >> 2);
    int hr = (r + 7) >> 2; if (hr > 35) hr = 35;
    int lc = (c <= 19) ? 0 : ((c - 9) >> 2);
    int hc = (c + 7) >> 2; if (hc > 35) hc = 35;

    if (lr <= hr && lc <= hc) {
        int cvec = c * 0x01010101, rvec = r * 0x01010101;
        float W = 1.0f, B = 0.0f;
        int cnt = 1;

        if (hc < lr) {
            for (int px = lc; px <= hc; ++px) {
                int pbase = (px * NGRID + lr) * NBC + bc;
                for (int py = lr; py <= hr; ++py, pbase += NBC)
                    read_pos(pbase, cvec, rvec, 2.0f, W, B);
            }
        } else if (hr < lc) {
            int T = 0;
            for (int px = lr; px <= hr; ++px) {
                int pbase = (px * NGRID + lc) * NBC + bc;
                for (int py = lc; py <= hc; ++py, pbase += NBC)
                    T += inc_pos(pbase, cvec, rvec);
            }
            cnt = 1 + T;
            W = s_rcp[cnt];
            float bw = 1.0f + s_rcp[cnt];
            for (int px = lc; px <= hc; ++px) {
                int pbase = (px * NGRID + lr) * NBC + bc;
                for (int py = lr; py <= hr; ++py, pbase += NBC)
                    read_pos(pbase, cvec, rvec, bw, W, B);
            }
        } else {
            float bw = 2.0f;
            int pmin = min(lr, lc), pmax = max(hr, hc);
            for (int px = pmin; px <= pmax; ++px) {
                bool cR = (px >= lc) & (px <= hc);
                bool cI = (px >= lr) & (px <= hr);
                if (cR & cI) {
                    int pbase = (px * NGRID + pmin) * NBC + bc;
                    for (int py = pmin; py <= pmax; ++py, pbase += NBC) {
                        bool pR = (py >= lr) & (py <= hr);
                        bool pC = (py >= lc) & (py <= hc);
                        if (pR & pC)      mixed_pos(pbase, cvec, rvec, cnt, bw, W, B, s_rcp);
                        else if (pR)      read_pos(pbase, cvec, rvec, bw, W, B);
                        else if (pC) {
                            int k = inc_pos(pbase, cvec, rvec);
                            if (k) {
                                W *= (float)cnt * s_rcp[cnt + k];
                                cnt += k;
                                bw = 1.0f + s_rcp[cnt];
                            }
                        }
                    }
                } else if (cR) {
                    int pbase = (px * NGRID + lr) * NBC + bc;
                    for (int py = lr; py <= hr; ++py, pbase += NBC)
                        read_pos(pbase, cvec, rvec, bw, W, B);
                } else if (cI) {
                    int k = 0;
                    int pbase = (px * NGRID + lc) * NBC + bc;
                    for (int py = lc; py <= hc; ++py, pbase += NBC)
                        k += inc_pos(pbase, cvec, rvec);
                    if (k) {
                        W *= (float)cnt * s_rcp[cnt + k];
                        cnt += k;
                        bw = 1.0f + s_rcp[cnt];
                    }
                }
            }
        }
        v = (v0 + B) * __frcp_rn(W * (float)cnt);
    }

    out[(size_t)bc * (HH * WW) + pix] = v;
}

// ============================================================
extern "C" void kernel_launch(void* const* d_in, const int* in_sizes, int n_in,
                              void* d_out, int out_size) {
    const float* images = (const float*)d_in[0];
    const float* Wp = (const float*)d_in[1];
    const float* bp = (const float*)d_in[2];
    const float* pe = (const float*)d_in[3];
    const float* Wb = (const float*)d_in[4];
    const float* bb = (const float*)d_in[5];
    float* out = (float*)d_out;

    int prep_items = 49 * 49 + NPK * 49 + 49 * 3;
    prep_kernel<<<(prep_items + 127) / 128, 128>>>(Wp, bp, pe, Wb, bb);
    simtopk_kernel<<<NUNIT / 4, 128>>>(images);
    gemm_kernel<<<NROW / 128, 128>>>();

    dim3 gg((HH * WW) / 8);
    dim3 bl(32, 8);
    gather_kernel<<<gg, bl>>>(images, out);
}